// round 15
// baseline (speedup 1.0000x reference)
#include <cstdint>
#include <cuda_runtime.h>
#include <cuda_fp16.h>
#include <mma.h>

using namespace nvcuda;

#define OUT_F  2048
#define IN_F   2048
#define NNZ    209715
#define TOKENS 16384

#define BM 128
#define BN 128
#define BK 64
#define KITERS (IN_F / BK)     // 32
#define NSTAGE 3
#define LDH 72                 // halves per smem row: 64 + 8 pad (144B)
#define TILE_HALVES (128 * LDH)
#define STAGE_HALVES (2 * TILE_HALVES)
#define SMEM_BYTES (NSTAGE * STAGE_HALVES * 2)   // 110,592 B per CTA

// Scratch (device globals: no allocation allowed).
__device__ __half g_Wh[(size_t)OUT_F * IN_F];    // fp16 weight (8 MB)
__device__ __half g_Xh[(size_t)TOKENS * IN_F];   // fp16 activations (67 MB)

__device__ __forceinline__ unsigned h2_as_u32(__half2 h) {
    unsigned u;
    memcpy(&u, &h, 4);
    return u;
}

// ---------------------------------------------------------------------------
// Kernel 1: dequantize int4 base directly into fp16 g_Wh.
// ---------------------------------------------------------------------------
__global__ void dequant_kernel(const int* __restrict__ packed,
                               const float* __restrict__ scales) {
    int idx = blockIdx.x * blockDim.x + threadIdx.x;   // over OUT_F * IN_F/2
    const int total = OUT_F * (IN_F / 2);
    if (idx >= total) return;
    int o = idx >> 10;                                 // IN_F/2 == 1024
    int p = packed[idx];
    float s = scales[o];
    float a = (float)((p & 0xF) - 8) * s;
    float b = (float)(((p >> 4) & 0xF) - 8) * s;
    reinterpret_cast<__half2*>(g_Wh)[idx] = __floats2half2_rn(a, b);
}

// ---------------------------------------------------------------------------
// Kernel 2: scatter COO residual with fp16 atomicAdd (duplicates accumulate).
// ---------------------------------------------------------------------------
__global__ void scatter_kernel(const float* __restrict__ vals,
                               const int* __restrict__ rows,
                               const int* __restrict__ cols) {
    int i = blockIdx.x * blockDim.x + threadIdx.x;
    if (i >= NNZ) return;
    atomicAdd(&g_Wh[(size_t)rows[i] * IN_F + cols[i]], __float2half(vals[i]));
}

// ---------------------------------------------------------------------------
// Kernel 3: x fp32 -> fp16 (2x float4 in, 1x uint4 out per thread).
// ---------------------------------------------------------------------------
__global__ void convert_x_kernel(const float* __restrict__ x) {
    size_t i = (size_t)blockIdx.x * blockDim.x + threadIdx.x;  // 8-float group
    float4 v0 = reinterpret_cast<const float4*>(x)[i * 2 + 0];
    float4 v1 = reinterpret_cast<const float4*>(x)[i * 2 + 1];
    uint4 o;
    o.x = h2_as_u32(__floats2half2_rn(v0.x, v0.y));
    o.y = h2_as_u32(__floats2half2_rn(v0.z, v0.w));
    o.z = h2_as_u32(__floats2half2_rn(v1.x, v1.y));
    o.w = h2_as_u32(__floats2half2_rn(v1.z, v1.w));
    reinterpret_cast<uint4*>(g_Xh)[i] = o;
}

// ---------------------------------------------------------------------------
// GEMM: out[t,o] = sum_i X[t,i] * W[o,i]; fp16 wmma (16x16x16), fp32 acc.
// CTA tile 128x128, BK=64, 3-stage cp.async, 4 warps (2x2), warp tile 64x64.
// One __syncthreads per K-iteration of 64.
// ---------------------------------------------------------------------------
__device__ __forceinline__ void cpasync16(void* smem, const void* gmem) {
    unsigned s = (unsigned)__cvta_generic_to_shared(smem);
    asm volatile("cp.async.cg.shared.global [%0], [%1], 16;" :: "r"(s), "l"(gmem));
}

extern __shared__ __half smh[];

__device__ __forceinline__ void load_stage(__half* stg, const __half* gA,
                                           const __half* gB, int k0, int tid) {
    // per tile: 128 rows x 64 halves (128B) = 1024 x 16B chunks; A+B = 2048.
    // 128 threads -> 16 chunks each (8 A + 8 B).
    #pragma unroll
    for (int i = 0; i < 8; i++) {
        int idx = i * 128 + tid;          // 0..1023
        int row = idx >> 3;               // 0..127
        int ch  = (idx & 7) * 8;          // half offset within 64
        __half* sa = stg + row * LDH + ch;
        cpasync16(sa,               gA + (size_t)row * IN_F + k0 + ch);
        cpasync16(sa + TILE_HALVES, gB + (size_t)row * IN_F + k0 + ch);
    }
}

__global__ __launch_bounds__(128, 2)
void gemm_kernel(float* __restrict__ out) {
    const int tid  = threadIdx.x;
    const int warp = tid >> 5;
    const int wm   = warp >> 1;           // 0..1
    const int wn   = warp & 1;            // 0..1

    const int m0 = blockIdx.y * BM;
    const int n0 = blockIdx.x * BN;

    const __half* gA = g_Xh + (size_t)m0 * IN_F;
    const __half* gB = g_Wh + (size_t)n0 * IN_F;

    wmma::fragment<wmma::accumulator, 16, 16, 16, float> acc[4][4];
    #pragma unroll
    for (int i = 0; i < 4; i++)
        #pragma unroll
        for (int j = 0; j < 4; j++)
            wmma::fill_fragment(acc[i][j], 0.0f);

    // prologue: fill NSTAGE-1 stages
    #pragma unroll
    for (int s = 0; s < NSTAGE - 1; s++) {
        load_stage(smh + s * STAGE_HALVES, gA, gB, s * BK, tid);
        asm volatile("cp.async.commit_group;" ::: "memory");
    }

    for (int kt = 0; kt < KITERS; kt++) {
        // outstanding groups newer than kt: just stage kt+1 (if it exists)
        if (kt < KITERS - 1) asm volatile("cp.async.wait_group 1;" ::: "memory");
        else                 asm volatile("cp.async.wait_group 0;" ::: "memory");
        __syncthreads();   // all warps done with stage kt-1 -> slot reusable

        if (kt + NSTAGE - 1 < KITERS) {
            load_stage(smh + ((kt + NSTAGE - 1) % NSTAGE) * STAGE_HALVES,
                       gA, gB, (kt + NSTAGE - 1) * BK, tid);
            asm volatile("cp.async.commit_group;" ::: "memory");
        }

        const __half* sA = smh + (kt % NSTAGE) * STAGE_HALVES;
        const __half* sB = sA + TILE_HALVES;

        #pragma unroll
        for (int ks = 0; ks < 4; ks++) {    // four K=16 steps per BK=64
            const int kk = ks * 16;
            wmma::fragment<wmma::matrix_a, 16, 16, 16, __half, wmma::row_major> af[4];
            wmma::fragment<wmma::matrix_b, 16, 16, 16, __half, wmma::col_major> bf[4];
            #pragma unroll
            for (int i = 0; i < 4; i++)
                wmma::load_matrix_sync(af[i], sA + (wm * 64 + i * 16) * LDH + kk, LDH);
            #pragma unroll
            for (int j = 0; j < 4; j++)
                wmma::load_matrix_sync(bf[j], sB + (wn * 64 + j * 16) * LDH + kk, LDH);
            #pragma unroll
            for (int i = 0; i < 4; i++)
                #pragma unroll
                for (int j = 0; j < 4; j++)
                    wmma::mma_sync(acc[i][j], af[i], bf[j], acc[i][j]);
        }
    }

    #pragma unroll
    for (int i = 0; i < 4; i++)
        #pragma unroll
        for (int j = 0; j < 4; j++) {
            float* dst = out + (size_t)(m0 + wm * 64 + i * 16) * OUT_F
                             + n0 + wn * 64 + j * 16;
            wmma::store_matrix_sync(dst, acc[i][j], OUT_F, wmma::mem_row_major);
        }
}

// ---------------------------------------------------------------------------
// Inputs (metadata order):
//   0: x float32 [4,4096,2048]   1: base_packed int32 [2048,1024]
//   2: scales float32 [2048]     3: ortho_vals float32 [209715]
//   4: ortho_rows int32          5: ortho_cols int32
// output: float32 [16384, 2048]
// ---------------------------------------------------------------------------
extern "C" void kernel_launch(void* const* d_in, const int* in_sizes, int n_in,
                              void* d_out, int out_size) {
    const float* x      = (const float*)d_in[0];
    const int*   packed = (const int*)  d_in[1];
    const float* scales = (const float*)d_in[2];
    const float* ovals  = (const float*)d_in[3];
    const int*   orows  = (const int*)  d_in[4];
    const int*   ocols  = (const int*)  d_in[5];
    float*       out    = (float*)d_out;

    dequant_kernel<<<(OUT_F * (IN_F / 2) + 255) / 256, 256>>>(packed, scales);
    scatter_kernel<<<(NNZ + 255) / 256, 256>>>(ovals, orows, ocols);
    convert_x_kernel<<<((size_t)TOKENS * IN_F / 8) / 256, 256>>>(x);

    cudaFuncSetAttribute(gemm_kernel,
                         cudaFuncAttributeMaxDynamicSharedMemorySize, SMEM_BYTES);
    dim3 grid(OUT_F / BN, TOKENS / BM);   // x-fastest: n-tiles share x tile in L2
    gemm_kernel<<<grid, 128, SMEM_BYTES>>>(out);
}